// round 10
// baseline (speedup 1.0000x reference)
#include <cuda_runtime.h>
#include <cuda_bf16.h>
#include <math.h>

// ---------------- problem constants ----------------
#define BATCH   256
#define IMG     224
#define CCH     3
#define NP      16
#define PS      14
#define INPUT_D 588           // 3*14*14
#define HIDDEN  128
#define NHEADS  2
#define DHEAD   64
#define NBLOCKS 2
#define MLP     512
#define OUTD    1000
#define SEQ     257           // 16*16 + 1
#define MTOK    (BATCH*SEQ)   // 65792 = 514*128
#define MPATCH  (BATCH*NP*NP) // 65536

// ---------------- packed f32x2 helpers (Blackwell sm_103a) ----------------
#define FMA2(d, a, b) asm("fma.rn.f32x2 %0, %1, %2, %0;" : "+l"(d) : "l"(a), "l"(b))
#define MUL2(d, a)    asm("mul.rn.f32x2 %0, %0, %1;"     : "+l"(d) : "l"(a))
#define ADD2(d, a)    asm("add.rn.f32x2 %0, %0, %1;"     : "+l"(d) : "l"(a))
#define BCAST2(d, f)  asm("mov.b64 %0, {%1, %1};" : "=l"(d) : "r"(__float_as_uint(f)))
#define PACK2(d, f0, f1) asm("mov.b64 %0, {%1, %2};" : "=l"(d) : "r"(__float_as_uint(f0)), "r"(__float_as_uint(f1)))
#define UNPACK2(u0, u1, s) asm("mov.b64 {%0, %1}, %2;" : "=r"(u0), "=r"(u1) : "l"(s))

// ---------------- scratch (device globals; no allocation allowed) ----------------
__device__ float g_out[MTOK*HIDDEN];        // residual stream
__device__ float g_x  [MTOK*HIDDEN];        // LN output
__device__ float g_qkv[MTOK*3*HIDDEN];      // fused q|k|v
__device__ float g_h1 [MTOK*MLP];           // MLP hidden
__device__ float g_mapWT[INPUT_D*HIDDEN];
__device__ float g_qkvW[NBLOCKS*HIDDEN*3*HIDDEN];   // [blk][d][3*128] block-diagonal combined
__device__ float g_qkvB[NBLOCKS*3*HIDDEN];
__device__ float g_w1T[NBLOCKS*HIDDEN*MLP];
__device__ float g_w2T[NBLOCKS*MLP*HIDDEN];
__device__ float g_headWT[HIDDEN*OUTD];
__device__ float g_pos[SEQ*HIDDEN];

// ---------------- prep: weight transposes, combined QKV, positional table ----------------
#define S0 (INPUT_D*HIDDEN)            // mapWT       75264
#define S1 (NBLOCKS*HIDDEN*3*HIDDEN)   // qkvW        98304
#define S2 (NBLOCKS*3*HIDDEN)          // qkvB          768
#define S3 (NBLOCKS*HIDDEN*MLP)        // w1T        131072
#define S4 (NBLOCKS*MLP*HIDDEN)        // w2T        131072
#define S5 (HIDDEN*OUTD)               // headWT     128000
#define S6 (SEQ*HIDDEN)                // pos         32896
#define PREP_TOTAL (S0+S1+S2+S3+S4+S5+S6)

__global__ void prep_kernel(const float* __restrict__ mapW,
                            const float* __restrict__ qW, const float* __restrict__ qb,
                            const float* __restrict__ kW, const float* __restrict__ kb,
                            const float* __restrict__ vW, const float* __restrict__ vb,
                            const float* __restrict__ w1, const float* __restrict__ w2,
                            const float* __restrict__ headW)
{
    for (int idx = blockIdx.x*blockDim.x + threadIdx.x; idx < PREP_TOTAL;
         idx += gridDim.x*blockDim.x) {
        int t = idx;
        if (t < S0) {                       // mapWT[d][e] = mapW[e][d]
            int d = t / HIDDEN, e = t % HIDDEN;
            g_mapWT[t] = mapW[e*INPUT_D + d];
            continue;
        }
        t -= S0;
        if (t < S1) {                       // combined block-diagonal QKV weight
            int blk = t / (HIDDEN*3*HIDDEN);
            int rr  = t % (HIDDEN*3*HIDDEN);
            int dfull = rr / (3*HIDDEN);
            int col   = rr % (3*HIDDEN);
            int sect  = col / HIDDEN;       // 0=q 1=k 2=v
            int ef    = col % HIDDEN;
            int h = ef >> 6, e = ef & 63, d = dfull & 63;
            float val = 0.f;
            if ((dfull >> 6) == h) {
                const float* W = (sect==0)? qW : (sect==1)? kW : vW;
                val = W[(((blk*NHEADS)+h)*DHEAD + e)*DHEAD + d];
            }
            g_qkvW[t] = val;
            continue;
        }
        t -= S1;
        if (t < S2) {                       // combined bias
            int blk = t / (3*HIDDEN);
            int col = t % (3*HIDDEN);
            int sect = col / HIDDEN;
            int ef   = col % HIDDEN;
            int h = ef >> 6, e = ef & 63;
            const float* B = (sect==0)? qb : (sect==1)? kb : vb;
            g_qkvB[t] = B[((blk*NHEADS)+h)*DHEAD + e];
            continue;
        }
        t -= S2;
        if (t < S3) {                       // w1T[blk][k][n] = w1[blk][n][k]
            int blk = t / (HIDDEN*MLP);
            int rr  = t % (HIDDEN*MLP);
            int k = rr / MLP, n = rr % MLP;
            g_w1T[t] = w1[(blk*MLP + n)*HIDDEN + k];
            continue;
        }
        t -= S3;
        if (t < S4) {                       // w2T[blk][k][n] = w2[blk][n][k]
            int blk = t / (MLP*HIDDEN);
            int rr  = t % (MLP*HIDDEN);
            int k = rr / HIDDEN, n = rr % HIDDEN;
            g_w2T[t] = w2[(blk*HIDDEN + n)*MLP + k];
            continue;
        }
        t -= S4;
        if (t < S5) {                       // headWT[k][n] = headW[n][k]
            int k = t / OUTD, n = t % OUTD;
            g_headWT[t] = headW[n*HIDDEN + k];
            continue;
        }
        t -= S5;
        {                                   // positional embedding (fp64, matches numpy)
            int i = t / HIDDEN, j = t % HIDDEN;
            double ex   = (double)(j - (j & 1)) / (double)HIDDEN;
            double freq = pow(10000.0, ex);
            double arg  = (double)i / freq;
            g_pos[t] = (j & 1) ? (float)cos(arg) : (float)sin(arg);
        }
    }
}

// ---------------- cls token rows: out[b][0] = cls + pos[0] ----------------
__global__ void cls_pos_kernel(const float* __restrict__ cls)
{
    int idx = blockIdx.x*blockDim.x + threadIdx.x;     // 256*128
    if (idx >= BATCH*HIDDEN) return;
    int b = idx >> 7, j = idx & 127;
    g_out[(size_t)b*SEQ*HIDDEN + j] = cls[j] + g_pos[j];
}

// ---------------- patch-embed GEMM (LUT gather A) + pos add, 64x64 tiles ----------------
__global__ void __launch_bounds__(256)
patch_embed_kernel(const float* __restrict__ images,
                   const float* __restrict__ mapb)
{
    __shared__ __align__(16) float As[16][68];   // padded: avoids 16-way write conflicts
    __shared__ __align__(16) float Bs[16][64];
    __shared__ int coltab[INPUT_D];              // k -> image offset within a patch row-base
    __shared__ int rowbase[64];                  // tile row -> image base offset
    const int K = INPUT_D, N = HIDDEN;
    int tid  = threadIdx.x;
    int row0 = blockIdx.y * 64;
    int col0 = blockIdx.x * 64;
    int tr = tid >> 4, tc = tid & 15;

    // fill LUTs once per block
    for (int k = tid; k < INPUT_D; k += 256) {
        int cc = k / 196; int rem = k - cc*196;
        int u  = rem / 14; int v14 = rem - u*14;
        coltab[k] = cc*IMG*IMG + u*IMG + v14;
    }
    if (tid < 64) {
        int gr = row0 + tid;
        int b  = gr >> 8, patch = gr & 255;
        int py = patch >> 4, px = patch & 15;
        rowbase[tid] = b*CCH*IMG*IMG + (py*PS)*IMG + px*PS;
    }
    __syncthreads();

    float acc[4][4];
    #pragma unroll
    for (int i=0;i<4;i++)
        #pragma unroll
        for (int j=0;j<4;j++) acc[i][j]=0.f;

    for (int k0 = 0; k0 < K; k0 += 16) {
        #pragma unroll
        for (int i=0;i<4;i++) {
            int li = tid + i*256;
            int r = li >> 4, c = li & 15;
            int gk = k0 + c;
            float v = 0.f;
            if (gk < K)
                v = images[(size_t)(rowbase[r] + coltab[gk])];
            As[c][r] = v;
        }
        #pragma unroll
        for (int i=0;i<4;i++) {
            int li = tid + i*256;
            int r = li >> 6, c = li & 63;
            int gk = k0 + r;
            Bs[r][c] = (gk < K) ? g_mapWT[(size_t)gk*N + col0 + c] : 0.f;
        }
        __syncthreads();
        #pragma unroll
        for (int kk=0;kk<16;kk++){
            float4 av = *reinterpret_cast<const float4*>(&As[kk][tr*4]);
            float4 bv = *reinterpret_cast<const float4*>(&Bs[kk][tc*4]);
            acc[0][0]+=av.x*bv.x; acc[0][1]+=av.x*bv.y; acc[0][2]+=av.x*bv.z; acc[0][3]+=av.x*bv.w;
            acc[1][0]+=av.y*bv.x; acc[1][1]+=av.y*bv.y; acc[1][2]+=av.y*bv.z; acc[1][3]+=av.y*bv.w;
            acc[2][0]+=av.z*bv.x; acc[2][1]+=av.z*bv.y; acc[2][2]+=av.z*bv.z; acc[2][3]+=av.z*bv.w;
            acc[3][0]+=av.w*bv.x; acc[3][1]+=av.w*bv.y; acc[3][2]+=av.w*bv.z; acc[3][3]+=av.w*bv.w;
        }
        __syncthreads();
    }
    #pragma unroll
    for (int i=0;i<4;i++){
        int gr = row0 + tr*4 + i;
        int b  = gr >> 8, patch = gr & 255;
        size_t drow = (size_t)b*SEQ + 1 + patch;
        #pragma unroll
        for (int j=0;j<4;j++){
            int cc = col0 + tc*4 + j;
            g_out[drow*HIDDEN + cc] = acc[i][j] + mapb[cc] + g_pos[(1+patch)*HIDDEN + cc];
        }
    }
}

// ---------------- 128x128-tile SGEMM, double-buffered smem, packed f32x2 math ----------
// 256 threads, 8x8 microtile as 8x(4 pairs). M%128==0, N%128==0, K%16==0.
#define GF_GELU 1
#define GF_ACC  2
__global__ void __launch_bounds__(256, 2)
sgemm128_kernel(const float* __restrict__ A, const float* __restrict__ B,
                const float* __restrict__ bias, float* __restrict__ C,
                int N, int K, int flags)
{
    __shared__ __align__(16) float As[2][16][136];
    __shared__ __align__(16) float Bs[2][16][128];
    int tid  = threadIdx.x;
    int row0 = blockIdx.y * 128;
    int col0 = blockIdx.x * 128;
    int tr = tid >> 4, tc = tid & 15;            // 16x16 thread grid

    // per-thread load coordinates (constant over k)
    int ra  = (tid*2)   >> 2, kqa = (tid*2)   & 3;    // A elem 0
    int ra2 = (tid*2+1) >> 2, kqa2= (tid*2+1) & 3;    // A elem 1
    int rb  = (tid*2)   >> 5, cb  = (tid*2)   & 31;   // B elem 0
    int rb2 = (tid*2+1) >> 5, cb2 = (tid*2+1) & 31;   // B elem 1

    // packed accumulators: accp[i][jp] = cols pair; i: rows (0..3 -> tr*4+i, 4..7 -> 64+tr*4+i-4)
    // jp: 0,1 -> cols tc*4 + {0,1},{2,3};  2,3 -> cols 64+tc*4 + {0,1},{2,3}
    unsigned long long accp[8][4];
    #pragma unroll
    for (int i=0;i<8;i++)
        #pragma unroll
        for (int jp=0;jp<4;jp++) accp[i][jp] = 0ULL;

    const int ntiles = K >> 4;

    // preload tile 0 into buffer 0
    {
        float4 a0 = *reinterpret_cast<const float4*>(&A[(size_t)(row0+ra )*K + kqa *4]);
        float4 a1 = *reinterpret_cast<const float4*>(&A[(size_t)(row0+ra2)*K + kqa2*4]);
        float4 b0 = *reinterpret_cast<const float4*>(&B[(size_t)(rb )*N + col0 + cb *4]);
        float4 b1 = *reinterpret_cast<const float4*>(&B[(size_t)(rb2)*N + col0 + cb2*4]);
        As[0][kqa *4+0][ra ]=a0.x; As[0][kqa *4+1][ra ]=a0.y; As[0][kqa *4+2][ra ]=a0.z; As[0][kqa *4+3][ra ]=a0.w;
        As[0][kqa2*4+0][ra2]=a1.x; As[0][kqa2*4+1][ra2]=a1.y; As[0][kqa2*4+2][ra2]=a1.z; As[0][kqa2*4+3][ra2]=a1.w;
        *reinterpret_cast<float4*>(&Bs[0][rb ][cb *4]) = b0;
        *reinterpret_cast<float4*>(&Bs[0][rb2][cb2*4]) = b1;
    }
    __syncthreads();

    int buf = 0;
    for (int t = 0; t < ntiles; t++) {
        float4 pa0, pa1, pb0, pb1;
        bool more = (t+1 < ntiles);
        if (more) {                           // prefetch next tile into registers
            int k0 = (t+1) << 4;
            pa0 = *reinterpret_cast<const float4*>(&A[(size_t)(row0+ra )*K + k0 + kqa *4]);
            pa1 = *reinterpret_cast<const float4*>(&A[(size_t)(row0+ra2)*K + k0 + kqa2*4]);
            pb0 = *reinterpret_cast<const float4*>(&B[(size_t)(k0+rb )*N + col0 + cb *4]);
            pb1 = *reinterpret_cast<const float4*>(&B[(size_t)(k0+rb2)*N + col0 + cb2*4]);
        }
        // compute current buffer: per kk, 32 FMA2 + 8 broadcast packs + 4 LDS.128
        #pragma unroll
        for (int kk=0;kk<16;kk++){
            float4 a0 = *reinterpret_cast<const float4*>(&As[buf][kk][tr*4]);
            float4 a1 = *reinterpret_cast<const float4*>(&As[buf][kk][tr*4+64]);
            ulonglong2 bq0 = *reinterpret_cast<const ulonglong2*>(&Bs[buf][kk][tc*4]);
            ulonglong2 bq1 = *reinterpret_cast<const ulonglong2*>(&Bs[buf][kk][tc*4+64]);
            unsigned long long bb0 = bq0.x, bb1 = bq0.y, bb2 = bq1.x, bb3 = bq1.y;
            float ar[8] = {a0.x,a0.y,a0.z,a0.w, a1.x,a1.y,a1.z,a1.w};
            #pragma unroll
            for (int i=0;i<8;i++){
                unsigned long long ab;
                BCAST2(ab, ar[i]);
                FMA2(accp[i][0], ab, bb0);
                FMA2(accp[i][1], ab, bb1);
                FMA2(accp[i][2], ab, bb2);
                FMA2(accp[i][3], ab, bb3);
            }
        }
        if (more) {                           // stage next tile into alternate buffer
            int nb = buf ^ 1;
            As[nb][kqa *4+0][ra ]=pa0.x; As[nb][kqa *4+1][ra ]=pa0.y; As[nb][kqa *4+2][ra ]=pa0.z; As[nb][kqa *4+3][ra ]=pa0.w;
            As[nb][kqa2*4+0][ra2]=pa1.x; As[nb][kqa2*4+1][ra2]=pa1.y; As[nb][kqa2*4+2][ra2]=pa1.z; As[nb][kqa2*4+3][ra2]=pa1.w;
            *reinterpret_cast<float4*>(&Bs[nb][rb ][cb *4]) = pb0;
            *reinterpret_cast<float4*>(&Bs[nb][rb2][cb2*4]) = pb1;
            __syncthreads();
            buf = nb;
        }
    }

    #pragma unroll
    for (int i=0;i<8;i++){
        size_t gr = row0 + (i>>2)*64 + tr*4 + (i&3);
        #pragma unroll
        for (int jp=0;jp<4;jp++){
            unsigned u0, u1;
            UNPACK2(u0, u1, accp[i][jp]);
            float v0 = __uint_as_float(u0), v1 = __uint_as_float(u1);
            int c0 = col0 + (jp>>1)*64 + tc*4 + (jp&1)*2;
            float w0 = v0 + bias[c0];
            float w1 = v1 + bias[c0+1];
            if (flags & GF_GELU) {
                w0 = 0.5f * w0 * (1.0f + erff(w0 * 0.70710678118654752f));
                w1 = 0.5f * w1 * (1.0f + erff(w1 * 0.70710678118654752f));
            }
            size_t idx = gr*N + c0;
            if (flags & GF_ACC) { C[idx] += w0; C[idx+1] += w1; }
            else                { C[idx]  = w0; C[idx+1]  = w1; }
        }
    }
}

// ---------------- layernorm: one warp per row, shuffle-only reductions ----------------
__global__ void __launch_bounds__(256)
ln_kernel(const float* __restrict__ x, const float* __restrict__ g,
          const float* __restrict__ b, float* __restrict__ y)
{
    int row  = blockIdx.x*8 + (threadIdx.x >> 5);   // 8 warps per block, 1 row each
    int lane = threadIdx.x & 31;
    const float4 v  = reinterpret_cast<const float4*>(x + (size_t)row*HIDDEN)[lane];
    float s = (v.x+v.y)+(v.z+v.w);
    #pragma unroll
    for (int o=16;o;o>>=1) s += __shfl_xor_sync(0xffffffffu, s, o);
    float mu = s * (1.0f/HIDDEN);
    float dx = v.x-mu, dy = v.y-mu, dz = v.z-mu, dw = v.w-mu;
    float s2 = (dx*dx+dy*dy)+(dz*dz+dw*dw);
    #pragma unroll
    for (int o=16;o;o>>=1) s2 += __shfl_xor_sync(0xffffffffu, s2, o);
    float rs = rsqrtf(s2 * (1.0f/HIDDEN) + 1e-5f);
    const float4 gg = reinterpret_cast<const float4*>(g)[lane];
    const float4 bb = reinterpret_cast<const float4*>(b)[lane];
    float4 o4;
    o4.x = dx*rs*gg.x + bb.x;
    o4.y = dy*rs*gg.y + bb.y;
    o4.z = dz*rs*gg.z + bb.z;
    o4.w = dw*rs*gg.w + bb.w;
    reinterpret_cast<float4*>(y + (size_t)row*HIDDEN)[lane] = o4;
}

// ---------------- fused flash attention, 2 blocks per (batch,head), packed f32x2 ------
// Query split: block handles [0,129) or [129,257). 160 threads -> 2 CTAs/SM.
// 16-key score tiles, double-buffered K/V staging: one barrier per tile.
#define KTILE 16
#define ATT_THREADS 160
#define QSPLIT0 129
#define ATT_NT   ((SEQ + KTILE - 1) / KTILE)   // 17 tiles
__global__ void __launch_bounds__(ATT_THREADS, 2)
attention_kernel(const float* __restrict__ qkv, float* __restrict__ out)
{
    __shared__ __align__(16) float Ks[2][KTILE*DHEAD];
    __shared__ __align__(16) float Vs[2][KTILE*DHEAD];
    int bhq = blockIdx.x;                 // (b,h,half)
    int half = bhq & 1;
    int bh   = bhq >> 1;
    int b  = bh >> 1, h = bh & 1;
    int tid = threadIdx.x;
    int r    = (half ? QSPLIT0 : 0) + tid;
    int rend = (half ? SEQ : QSPLIT0);
    bool act = (r < rend);
    const float scale = 0.125f;          // 1/sqrt(64)

    // per-thread staging element indices (tile has KTILE*16 = 256 float4 slots)
    int i0 = tid, i1 = tid + ATT_THREADS;           // i1 valid only when tid < 96
    int j0e = i0 >> 4, e0 = i0 & 15;
    int j1e = i1 >> 4, e1 = i1 & 15;
    const float4* qkv4 = reinterpret_cast<const float4*>(qkv);
    size_t bbase = (size_t)b*SEQ;

    unsigned long long qp[32];            // q pairs (scaled)
    unsigned long long accp[32];          // output accumulator pairs
    float m = -1e30f, l = 0.f;
    if (act) {
        const float4* qrow = qkv4 + (bbase + r)*(3*HIDDEN/4) + h*(DHEAD/4);
        #pragma unroll
        for (int e4=0;e4<DHEAD/4;e4++){
            float4 t = qrow[e4];
            PACK2(qp[e4*2+0], t.x*scale, t.y*scale);
            PACK2(qp[e4*2+1], t.z*scale, t.w*scale);
        }
        #pragma unroll
        for (int e2=0;e2<32;e2++) accp[e2] = 0ULL;
    }

    // preload tile 0 (full KTILE rows; tile 0 always full since SEQ>KTILE)
    {
        size_t rb0 = (bbase + j0e)*(3*HIDDEN/4) + h*(DHEAD/4);
        reinterpret_cast<float4*>(Ks[0])[i0] = qkv4[rb0 + (HIDDEN/4)   + e0];
        reinterpret_cast<float4*>(Vs[0])[i0] = qkv4[rb0 + (2*HIDDEN/4) + e0];
        if (i1 < KTILE*16) {
            size_t rb1 = (bbase + j1e)*(3*HIDDEN/4) + h*(DHEAD/4);
            reinterpret_cast<float4*>(Ks[0])[i1] = qkv4[rb1 + (HIDDEN/4)   + e1];
            reinterpret_cast<float4*>(Vs[0])[i1] = qkv4[rb1 + (2*HIDDEN/4) + e1];
        }
    }
    __syncthreads();

    int buf = 0;
    for (int t = 0; t < ATT_NT; t++) {
        int j0 = t*KTILE;
        int jn = SEQ - j0; if (jn > KTILE) jn = KTILE;
        bool more = (t+1 < ATT_NT);
        // prefetch next tile into registers
        float4 pk0, pv0, pk1, pv1;
        bool v0f = false, v1f = false;
        if (more) {
            int nj0 = j0 + KTILE;
            int jnn = SEQ - nj0; if (jnn > KTILE) jnn = KTILE;
            int lim = jnn*16;
            v0f = (i0 < lim);
            v1f = (i1 < lim);
            if (v0f) {
                size_t rb = (bbase + nj0 + j0e)*(3*HIDDEN/4) + h*(DHEAD/4);
                pk0 = qkv4[rb + (HIDDEN/4)   + e0];
                pv0 = qkv4[rb + (2*HIDDEN/4) + e0];
            }
            if (v1f) {
                size_t rb = (bbase + nj0 + j1e)*(3*HIDDEN/4) + h*(DHEAD/4);
                pk1 = qkv4[rb + (HIDDEN/4)   + e1];
                pv1 = qkv4[rb + (2*HIDDEN/4) + e1];
            }
        }
        // compute on current buffer
        if (act) {
            float s[KTILE];
            float tmax = -1e30f;
            for (int j = 0; j < jn; j++) {
                const ulonglong2* kj = reinterpret_cast<const ulonglong2*>(Ks[buf] + j*DHEAD);
                unsigned long long sp0 = 0ULL, sp1 = 0ULL;
                #pragma unroll
                for (int e8=0;e8<16;e8++){
                    ulonglong2 kv = kj[e8];
                    FMA2(sp0, qp[2*e8+0], kv.x);
                    FMA2(sp1, qp[2*e8+1], kv.y);
                }
                ADD2(sp0, sp1);
                unsigned u0, u1;
                UNPACK2(u0, u1, sp0);
                s[j] = __uint_as_float(u0) + __uint_as_float(u1);
                tmax = fmaxf(tmax, s[j]);
            }
            float mnew = fmaxf(m, tmax);
            float corr = expf(m - mnew);
            l *= corr;
            {
                unsigned long long cb;
                BCAST2(cb, corr);
                #pragma unroll
                for (int e2=0;e2<32;e2++) MUL2(accp[e2], cb);
            }
            m = mnew;
            for (int j = 0; j < jn; j++) {
                float p = expf(s[j] - mnew);
                l += p;
                unsigned long long pb;
                BCAST2(pb, p);
                const ulonglong2* vj = reinterpret_cast<const ulonglong2*>(Vs[buf] + j*DHEAD);
                #pragma unroll
                for (int e8=0;e8<16;e8++){
                    ulonglong2 vv = vj[e8];
                    FMA2(accp[2*e8+0], pb, vv.x);
                    FMA2(accp[2*e8+1], pb, vv.y);
                }
            }
        }
        // store prefetched tile, single barrier per iteration
        if (more) {
            int nb = buf ^ 1;
            if (v0f) {
                reinterpret_cast<float4*>(Ks[nb])[i0] = pk0;
                reinterpret_cast<float4*>(Vs[nb])[i0] = pv0;
            }
            if (v1f) {
                reinterpret_cast<float4*>(Ks[nb])[i1] = pk1;
                reinterpret_cast<float4*>(Vs[nb])[i1] = pv1;
            }
            __syncthreads();
            buf = nb;
        }
    }
    if (act) {
        float inv = 1.0f / l;
        float4* orow4 = reinterpret_cast<float4*>(out + (bbase + r)*HIDDEN + h*DHEAD);
        #pragma unroll
        for (int e4=0;e4<DHEAD/4;e4++){
            float4 ov = orow4[e4];
            unsigned u0,u1,u2,u3;
            UNPACK2(u0, u1, accp[2*e4+0]);
            UNPACK2(u2, u3, accp[2*e4+1]);
            ov.x += __uint_as_float(u0)*inv;
            ov.y += __uint_as_float(u1)*inv;
            ov.z += __uint_as_float(u2)*inv;
            ov.w += __uint_as_float(u3)*inv;
            orow4[e4] = ov;
        }
    }
}

// ---------------- classifier head + softmax, one block per batch element ----------------
__global__ void __launch_bounds__(256)
head_kernel(const float* __restrict__ headb, float* __restrict__ dst)
{
    __shared__ float xs[HIDDEN];
    __shared__ float logits[OUTD];
    __shared__ float red[8];
    __shared__ float sval;
    int b = blockIdx.x, tid = threadIdx.x;
    if (tid < HIDDEN) xs[tid] = g_out[(size_t)b*SEQ*HIDDEN + tid];
    __syncthreads();
    for (int n = tid; n < OUTD; n += 256) {
        float s = headb[n];
        #pragma unroll 8
        for (int k = 0; k < HIDDEN; k++) s += xs[k]*g_headWT[(size_t)k*OUTD + n];
        logits[n] = s;
    }
    __syncthreads();
    // max
    float mv = -1e30f;
    for (int n = tid; n < OUTD; n += 256) mv = fmaxf(mv, logits[n]);
    #pragma unroll
    for (int o=16;o;o>>=1) mv = fmaxf(mv, __shfl_xor_sync(0xffffffffu, mv, o));
    if ((tid & 31) == 0) red[tid>>5] = mv;
    __syncthreads();
    if (tid == 0) {
        float t = red[0];
        #pragma unroll
        for (int i=1;i<8;i++) t = fmaxf(t, red[i]);
        sval = t;
    }
    __syncthreads();
    float mx = sval;
    float sum = 0.f;
    for (int n = tid; n < OUTD; n += 256) {
        float e = expf(logits[n] - mx);
        logits[n] = e;
        sum += e;
    }
    #pragma unroll
    for (int o=16;o;o>>=1) sum += __shfl_xor_sync(0xffffffffu, sum, o);
    if ((tid & 31) == 0) red[tid>>5] = sum;
    __syncthreads();
    if (tid == 0) {
        float t = 0.f;
        #pragma unroll
        for (int i=0;i<8;i++) t += red[i];
        sval = t;
    }
    __syncthreads();
    float inv = 1.0f / sval;
    for (int n = tid; n < OUTD; n += 256)
        dst[(size_t)b*OUTD + n] = logits[n]*inv;
}

// ---------------- launch ----------------
extern "C" void kernel_launch(void* const* d_in, const int* in_sizes, int n_in,
                              void* d_out, int out_size)
{
    const float* images = (const float*)d_in[0];
    const float* mapW   = (const float*)d_in[1];
    const float* mapb   = (const float*)d_in[2];
    const float* cls    = (const float*)d_in[3];
    const float* qW     = (const float*)d_in[4];
    const float* qb     = (const float*)d_in[5];
    const float* kW     = (const float*)d_in[6];
    const float* kb     = (const float*)d_in[7];
    const float* vW     = (const float*)d_in[8];
    const float* vb     = (const float*)d_in[9];
    const float* ln1g   = (const float*)d_in[10];
    const float* ln1b   = (const float*)d_in[11];
    const float* ln2g   = (const float*)d_in[12];
    const float* ln2b   = (const float*)d_in[13];
    const float* w1     = (const float*)d_in[14];
    const float* b1     = (const float*)d_in[15];
    const float* w2     = (const float*)d_in[16];
    const float* b2     = (const float*)d_in[17];
    const float* headW  = (const float*)d_in[18];
    const float* headb  = (const float*)d_in[19];
    float* dst = (float*)d_out;

    float *p_out, *p_x, *p_qkv, *p_h1, *p_qkvW, *p_qkvB, *p_w1T, *p_w2T;
    cudaGetSymbolAddress((void**)&p_out,  g_out);
    cudaGetSymbolAddress((void**)&p_x,    g_x);
    cudaGetSymbolAddress((void**)&p_qkv,  g_qkv);
    cudaGetSymbolAddress((void**)&p_h1,   g_h1);
    cudaGetSymbolAddress((void**)&p_qkvW, g_qkvW);
    cudaGetSymbolAddress((void**)&p_qkvB, g_qkvB);
    cudaGetSymbolAddress((void**)&p_w1T,  g_w1T);
    cudaGetSymbolAddress((void**)&p_w2T,  g_w2T);

    // weight prep (cheap, deterministic, runs inside graph)
    prep_kernel<<<(PREP_TOTAL+255)/256, 256>>>(mapW, qW, qb, kW, kb, vW, vb, w1, w2, headW);

    // tokens: cls row + patch embed (+pos)
    cls_pos_kernel<<<(BATCH*HIDDEN+255)/256, 256>>>(cls);
    patch_embed_kernel<<<dim3(HIDDEN/64, MPATCH/64), 256>>>(images, mapb);

    for (int blk = 0; blk < NBLOCKS; blk++) {
        // LN1 -> x  (8 rows per 256-thread block)
        ln_kernel<<<MTOK/8, 256>>>(p_out, ln1g + blk*HIDDEN, ln1b + blk*HIDDEN, p_x);
        // fused qkv projection: (MTOK,128) x (128,384)
        sgemm128_kernel<<<dim3(3*HIDDEN/128, MTOK/128), 256>>>(
            p_x, p_qkvW + (size_t)blk*HIDDEN*3*HIDDEN, p_qkvB + blk*3*HIDDEN,
            p_qkv, 3*HIDDEN, HIDDEN, 0);
        // flash attention with residual add into out (query-split, 2 blocks per bh)
        attention_kernel<<<BATCH*NHEADS*2, ATT_THREADS>>>(p_qkv, p_out);
        // LN2 -> x
        ln_kernel<<<MTOK/8, 256>>>(p_out, ln2g + blk*HIDDEN, ln2b + blk*HIDDEN, p_x);
        // MLP up + gelu
        sgemm128_kernel<<<dim3(MLP/128, MTOK/128), 256>>>(
            p_x, p_w1T + (size_t)blk*HIDDEN*MLP, b1 + blk*MLP,
            p_h1, MLP, HIDDEN, GF_GELU);
        // MLP down, accumulate into residual
        sgemm128_kernel<<<dim3(HIDDEN/128, MTOK/128), 256>>>(
            p_h1, p_w2T + (size_t)blk*MLP*HIDDEN, b2 + blk*HIDDEN,
            p_out, HIDDEN, MLP, GF_ACC);
    }

    // classifier head + softmax
    head_kernel<<<BATCH, 256>>>(headb, dst);
    (void)in_sizes; (void)n_in; (void)out_size;
}

// round 15
// speedup vs baseline: 1.1691x; 1.1691x over previous
#include <cuda_runtime.h>
#include <cuda_bf16.h>
#include <math.h>
#include <cstdint>

// ---------------- problem constants ----------------
#define BATCH   256
#define IMG     224
#define CCH     3
#define NP      16
#define PS      14
#define INPUT_D 588           // 3*14*14
#define HIDDEN  128
#define NHEADS  2
#define DHEAD   64
#define NBLOCKS 2
#define MLP     512
#define OUTD    1000
#define SEQ     257           // 16*16 + 1
#define MTOK    (BATCH*SEQ)   // 65792 = 514*128
#define MPATCH  (BATCH*NP*NP) // 65536

__device__ __forceinline__ uint32_t smem_to_u32(const void* p) {
    uint32_t a;
    asm("{ .reg .u64 t; cvta.to.shared.u64 t, %1; cvt.u32.u64 %0, t; }" : "=r"(a) : "l"(p));
    return a;
}
__device__ __forceinline__ void ldsm_x4(uint32_t& r0, uint32_t& r1, uint32_t& r2, uint32_t& r3,
                                        uint32_t addr) {
    asm volatile("ldmatrix.sync.aligned.m8n8.x4.shared.b16 {%0,%1,%2,%3}, [%4];"
        : "=r"(r0), "=r"(r1), "=r"(r2), "=r"(r3) : "r"(addr));
}
__device__ __forceinline__ void mma_bf16(float* c, const uint32_t* a, const uint32_t* b) {
    asm volatile("mma.sync.aligned.m16n8k16.row.col.f32.bf16.bf16.f32 "
        "{%0,%1,%2,%3}, {%4,%5,%6,%7}, {%8,%9}, {%0,%1,%2,%3};"
        : "+f"(c[0]), "+f"(c[1]), "+f"(c[2]), "+f"(c[3])
        : "r"(a[0]), "r"(a[1]), "r"(a[2]), "r"(a[3]), "r"(b[0]), "r"(b[1]));
}

// ---------------- scratch (device globals; no allocation allowed) ----------------
__device__ float g_out[MTOK*HIDDEN];                 // residual stream (fp32)
__device__ float g_qkv[MTOK*3*HIDDEN];               // fused q|k|v (fp32)
__device__ __nv_bfloat16 g_xhi[MTOK*HIDDEN];         // LN output split
__device__ __nv_bfloat16 g_xlo[MTOK*HIDDEN];
__device__ __nv_bfloat16 g_h1hi[MTOK*MLP];           // MLP hidden split
__device__ __nv_bfloat16 g_h1lo[MTOK*MLP];
__device__ float g_mapWT[INPUT_D*HIDDEN];
__device__ __nv_bfloat16 g_qkvWhi[NBLOCKS*3*HIDDEN*HIDDEN];  // [blk][n=384][k=128]
__device__ __nv_bfloat16 g_qkvWlo[NBLOCKS*3*HIDDEN*HIDDEN];
__device__ float g_qkvB[NBLOCKS*3*HIDDEN];
__device__ __nv_bfloat16 g_w1hi[NBLOCKS*MLP*HIDDEN];         // native [n=512][k=128]
__device__ __nv_bfloat16 g_w1lo[NBLOCKS*MLP*HIDDEN];
__device__ __nv_bfloat16 g_w2hi[NBLOCKS*HIDDEN*MLP];         // native [n=128][k=512]
__device__ __nv_bfloat16 g_w2lo[NBLOCKS*HIDDEN*MLP];
__device__ float g_headWT[HIDDEN*OUTD];
__device__ float g_pos[SEQ*HIDDEN];

__device__ __forceinline__ void split_bf16(float x, __nv_bfloat16& hi, __nv_bfloat16& lo) {
    __nv_bfloat16 h = __float2bfloat16(x);
    hi = h;
    lo = __float2bfloat16(x - __bfloat162float(h));
}

// ---------------- prep ----------------
#define S0 (INPUT_D*HIDDEN)               // mapWT
#define S1 (NBLOCKS*3*HIDDEN*HIDDEN)      // qkvW split [blk][n][k]
#define S2 (NBLOCKS*3*HIDDEN)             // qkvB
#define S3 (NBLOCKS*MLP*HIDDEN)           // w1 split
#define S4 (NBLOCKS*HIDDEN*MLP)           // w2 split
#define S5 (HIDDEN*OUTD)                  // headWT
#define S6 (SEQ*HIDDEN)                   // pos
#define PREP_TOTAL (S0+S1+S2+S3+S4+S5+S6)

__global__ void prep_kernel(const float* __restrict__ mapW,
                            const float* __restrict__ qW, const float* __restrict__ qb,
                            const float* __restrict__ kW, const float* __restrict__ kb,
                            const float* __restrict__ vW, const float* __restrict__ vb,
                            const float* __restrict__ w1, const float* __restrict__ w2,
                            const float* __restrict__ headW)
{
    for (int idx = blockIdx.x*blockDim.x + threadIdx.x; idx < PREP_TOTAL;
         idx += gridDim.x*blockDim.x) {
        int t = idx;
        if (t < S0) { int d = t / HIDDEN, e = t % HIDDEN; g_mapWT[t] = mapW[e*INPUT_D + d]; continue; }
        t -= S0;
        if (t < S1) {                     // combined QKV weight [blk][n=384][k=128] split
            int blk = t / (3*HIDDEN*HIDDEN);
            int rr  = t % (3*HIDDEN*HIDDEN);
            int n = rr / HIDDEN, k = rr % HIDDEN;
            int sec  = n >> 7;            // 0=q 1=k 2=v
            int ef   = n & 127;
            int h = ef >> 6, e = ef & 63, d = k & 63;
            float val = 0.f;
            if ((k >> 6) == h) {
                const float* W = (sec==0)? qW : (sec==1)? kW : vW;
                val = W[(((blk*NHEADS)+h)*DHEAD + e)*DHEAD + d];
            }
            split_bf16(val, g_qkvWhi[t], g_qkvWlo[t]);
            continue;
        }
        t -= S1;
        if (t < S2) {
            int blk = t / (3*HIDDEN);
            int n   = t % (3*HIDDEN);
            int sec = n >> 7, ef = n & 127;
            int h = ef >> 6, e = ef & 63;
            const float* B = (sec==0)? qb : (sec==1)? kb : vb;
            g_qkvB[t] = B[((blk*NHEADS)+h)*DHEAD + e];
            continue;
        }
        t -= S2;
        if (t < S3) { split_bf16(w1[t], g_w1hi[t], g_w1lo[t]); continue; }
        t -= S3;
        if (t < S4) { split_bf16(w2[t], g_w2hi[t], g_w2lo[t]); continue; }
        t -= S4;
        if (t < S5) { int k = t / OUTD, n = t % OUTD; g_headWT[t] = headW[n*HIDDEN + k]; continue; }
        t -= S5;
        {
            int i = t / HIDDEN, j = t % HIDDEN;
            double ex   = (double)(j - (j & 1)) / (double)HIDDEN;
            double freq = pow(10000.0, ex);
            double arg  = (double)i / freq;
            g_pos[t] = (j & 1) ? (float)cos(arg) : (float)sin(arg);
        }
    }
}

// ---------------- cls token rows ----------------
__global__ void cls_pos_kernel(const float* __restrict__ cls)
{
    int idx = blockIdx.x*blockDim.x + threadIdx.x;
    if (idx >= BATCH*HIDDEN) return;
    int b = idx >> 7, j = idx & 127;
    g_out[(size_t)b*SEQ*HIDDEN + j] = cls[j] + g_pos[j];
}

// ---------------- patch-embed GEMM (LUT gather A) + pos add, 64x64 tiles (scalar fp32) --
__global__ void __launch_bounds__(256)
patch_embed_kernel(const float* __restrict__ images,
                   const float* __restrict__ mapb)
{
    __shared__ __align__(16) float As[16][68];
    __shared__ __align__(16) float Bs[16][64];
    __shared__ int coltab[INPUT_D];
    __shared__ int rowbase[64];
    const int K = INPUT_D, N = HIDDEN;
    int tid  = threadIdx.x;
    int row0 = blockIdx.y * 64;
    int col0 = blockIdx.x * 64;
    int tr = tid >> 4, tc = tid & 15;

    for (int k = tid; k < INPUT_D; k += 256) {
        int cc = k / 196; int rem = k - cc*196;
        int u  = rem / 14; int v14 = rem - u*14;
        coltab[k] = cc*IMG*IMG + u*IMG + v14;
    }
    if (tid < 64) {
        int gr = row0 + tid;
        int b  = gr >> 8, patch = gr & 255;
        int py = patch >> 4, px = patch & 15;
        rowbase[tid] = b*CCH*IMG*IMG + (py*PS)*IMG + px*PS;
    }
    __syncthreads();

    float acc[4][4];
    #pragma unroll
    for (int i=0;i<4;i++)
        #pragma unroll
        for (int j=0;j<4;j++) acc[i][j]=0.f;

    for (int k0 = 0; k0 < K; k0 += 16) {
        #pragma unroll
        for (int i=0;i<4;i++) {
            int li = tid + i*256;
            int r = li >> 4, c = li & 15;
            int gk = k0 + c;
            float v = 0.f;
            if (gk < K) v = images[(size_t)(rowbase[r] + coltab[gk])];
            As[c][r] = v;
        }
        #pragma unroll
        for (int i=0;i<4;i++) {
            int li = tid + i*256;
            int r = li >> 6, c = li & 63;
            int gk = k0 + r;
            Bs[r][c] = (gk < K) ? g_mapWT[(size_t)gk*N + col0 + c] : 0.f;
        }
        __syncthreads();
        #pragma unroll
        for (int kk=0;kk<16;kk++){
            float4 av = *reinterpret_cast<const float4*>(&As[kk][tr*4]);
            float4 bv = *reinterpret_cast<const float4*>(&Bs[kk][tc*4]);
            acc[0][0]+=av.x*bv.x; acc[0][1]+=av.x*bv.y; acc[0][2]+=av.x*bv.z; acc[0][3]+=av.x*bv.w;
            acc[1][0]+=av.y*bv.x; acc[1][1]+=av.y*bv.y; acc[1][2]+=av.y*bv.z; acc[1][3]+=av.y*bv.w;
            acc[2][0]+=av.z*bv.x; acc[2][1]+=av.z*bv.y; acc[2][2]+=av.z*bv.z; acc[2][3]+=av.z*bv.w;
            acc[3][0]+=av.w*bv.x; acc[3][1]+=av.w*bv.y; acc[3][2]+=av.w*bv.z; acc[3][3]+=av.w*bv.w;
        }
        __syncthreads();
    }
    #pragma unroll
    for (int i=0;i<4;i++){
        int gr = row0 + tr*4 + i;
        int b  = gr >> 8, patch = gr & 255;
        size_t drow = (size_t)b*SEQ + 1 + patch;
        #pragma unroll
        for (int j=0;j<4;j++){
            int cc = col0 + tc*4 + j;
            g_out[drow*HIDDEN + cc] = acc[i][j] + mapb[cc] + g_pos[(1+patch)*HIDDEN + cc];
        }
    }
}

// ---------------- split-bf16 mma.sync GEMM: D = A*B^T (+bias, gelu/acc/bf16out) --------
// A: [M,K] bf16 hi/lo (K-major), B: [N,K] bf16 hi/lo. 128x128 block tile, K chunk 32.
// 8 warps in 4(M)x2(N); warp tile 32x64; mma.m16n8k16 row.col bf16->f32.
#define GF_GELU 1
#define GF_ACC  2
#define GF_BF16 4
#define LDA 40   // padded row length (bf16 elems): conflict-free ldmatrix

__global__ void __launch_bounds__(256, 2)
sgemm_mma_kernel(const __nv_bfloat16* __restrict__ Ahi, const __nv_bfloat16* __restrict__ Alo,
                 const __nv_bfloat16* __restrict__ Bhi, const __nv_bfloat16* __restrict__ Blo,
                 const float* __restrict__ bias, float* __restrict__ C,
                 __nv_bfloat16* __restrict__ Chi, __nv_bfloat16* __restrict__ Clo,
                 int N, int K, int flags)
{
    __shared__ __align__(16) __nv_bfloat16 As[2][128][LDA];   // [hi/lo][row][k]
    __shared__ __align__(16) __nv_bfloat16 Bs[2][128][LDA];
    int tid  = threadIdx.x;
    int wid  = tid >> 5, lane = tid & 31;
    int warp_m = wid >> 1, warp_n = wid & 1;
    int row0 = blockIdx.y * 128;
    int col0 = blockIdx.x * 128;

    float acc[2][8][4];
    #pragma unroll
    for (int mt=0;mt<2;mt++)
        #pragma unroll
        for (int nt=0;nt<8;nt++)
            #pragma unroll
            for (int r=0;r<4;r++) acc[mt][nt][r]=0.f;

    // ldmatrix lane addressing within a 16x16 (A) / 16(n)x16(k) (B pair) tile
    int lrow = (lane & 7) + ((lane >> 3) & 1) * 8;   // 0..15
    int lk   = (lane >> 4) * 8;                      // 0 or 8

    const int nchunks = K >> 5;                      // K/32
    for (int c = 0; c < nchunks; c++) {
        int k0 = c << 5;
        // stage 4 tiles (Ahi, Alo, Bhi, Blo): 2048 uint4, 8 per thread
        #pragma unroll
        for (int it = 0; it < 8; it++) {
            int idx = tid + it*256;                  // 0..2047
            int mat = idx >> 9;                      // 0:Ahi 1:Alo 2:Bhi 3:Blo
            int s   = idx & 511;
            int row = s >> 2, seg = s & 3;           // 4 segs of 8 bf16 = 32 k
            const __nv_bfloat16* src;
            if      (mat == 0) src = Ahi + (size_t)(row0+row)*K + k0 + seg*8;
            else if (mat == 1) src = Alo + (size_t)(row0+row)*K + k0 + seg*8;
            else if (mat == 2) src = Bhi + (size_t)(col0+row)*K + k0 + seg*8;
            else               src = Blo + (size_t)(col0+row)*K + k0 + seg*8;
            uint4 v = *reinterpret_cast<const uint4*>(src);
            __nv_bfloat16* dst = (mat < 2) ? &As[mat][row][seg*8] : &Bs[mat-2][row][seg*8];
            *reinterpret_cast<uint4*>(dst) = v;
        }
        __syncthreads();
        #pragma unroll
        for (int k16 = 0; k16 < 32; k16 += 16) {
            #pragma unroll
            for (int combo = 0; combo < 3; combo++) {
                // combo 0: Ahi*Bhi, 1: Ahi*Blo, 2: Alo*Bhi
                const __nv_bfloat16 (*Asrc)[LDA] = (combo == 2) ? As[1] : As[0];
                const __nv_bfloat16 (*Bsrc)[LDA] = (combo == 1) ? Bs[1] : Bs[0];
                uint32_t a[2][4];
                #pragma unroll
                for (int mt = 0; mt < 2; mt++) {
                    uint32_t addr = smem_to_u32(&Asrc[warp_m*32 + mt*16 + lrow][k16 + lk]);
                    ldsm_x4(a[mt][0], a[mt][1], a[mt][2], a[mt][3], addr);
                }
                uint32_t b[8][2];
                #pragma unroll
                for (int np = 0; np < 4; np++) {     // pairs of n-tiles (16 n rows)
                    uint32_t addr = smem_to_u32(&Bsrc[warp_n*64 + np*16 + lrow][k16 + lk]);
                    uint32_t r0, r1, r2, r3;
                    ldsm_x4(r0, r1, r2, r3, addr);
                    b[np*2  ][0] = r0; b[np*2  ][1] = r2;
                    b[np*2+1][0] = r1; b[np*2+1][1] = r3;
                }
                #pragma unroll
                for (int mt = 0; mt < 2; mt++)
                    #pragma unroll
                    for (int nt = 0; nt < 8; nt++)
                        mma_bf16(acc[mt][nt], a[mt], b[nt]);
            }
        }
        __syncthreads();
    }

    // epilogue: acc[mt][nt][r]: row = warp_m*32+mt*16+(lane>>2)+(r>=2?8:0),
    //                           col = warp_n*64+nt*8+(lane&3)*2+(r&1)
    int grow = row0 + warp_m*32 + (lane >> 2);
    int gcol = col0 + warp_n*64 + (lane & 3)*2;
    #pragma unroll
    for (int mt = 0; mt < 2; mt++) {
        #pragma unroll
        for (int h = 0; h < 2; h++) {
            size_t r = (size_t)(grow + mt*16 + h*8);
            #pragma unroll
            for (int nt = 0; nt < 8; nt++) {
                int cc = gcol + nt*8;
                float v0 = acc[mt][nt][h*2]   + bias[cc];
                float v1 = acc[mt][nt][h*2+1] + bias[cc+1];
                if (flags & GF_GELU) {
                    v0 = 0.5f * v0 * (1.0f + erff(v0 * 0.70710678118654752f));
                    v1 = 0.5f * v1 * (1.0f + erff(v1 * 0.70710678118654752f));
                }
                size_t gi = r*N + cc;
                if (flags & GF_BF16) {
                    __nv_bfloat16 h0, l0, h1, l1;
                    split_bf16(v0, h0, l0); split_bf16(v1, h1, l1);
                    Chi[gi] = h0; Chi[gi+1] = h1;
                    Clo[gi] = l0; Clo[gi+1] = l1;
                } else if (flags & GF_ACC) {
                    C[gi] += v0; C[gi+1] += v1;
                } else {
                    C[gi] = v0; C[gi+1] = v1;
                }
            }
        }
    }
}

// ---------------- layernorm: one warp per row, outputs bf16 hi/lo split ----------------
__global__ void __launch_bounds__(256)
ln_kernel(const float* __restrict__ x, const float* __restrict__ g,
          const float* __restrict__ b,
          __nv_bfloat16* __restrict__ yhi, __nv_bfloat16* __restrict__ ylo)
{
    int row  = blockIdx.x*8 + (threadIdx.x >> 5);
    int lane = threadIdx.x & 31;
    const float4 v = reinterpret_cast<const float4*>(x + (size_t)row*HIDDEN)[lane];
    float s = (v.x+v.y)+(v.z+v.w);
    #pragma unroll
    for (int o=16;o;o>>=1) s += __shfl_xor_sync(0xffffffffu, s, o);
    float mu = s * (1.0f/HIDDEN);
    float dx = v.x-mu, dy = v.y-mu, dz = v.z-mu, dw = v.w-mu;
    float s2 = (dx*dx+dy*dy)+(dz*dz+dw*dw);
    #pragma unroll
    for (int o=16;o;o>>=1) s2 += __shfl_xor_sync(0xffffffffu, s2, o);
    float rs = rsqrtf(s2 * (1.0f/HIDDEN) + 1e-5f);
    const float4 gg = reinterpret_cast<const float4*>(g)[lane];
    const float4 bb = reinterpret_cast<const float4*>(b)[lane];
    float o0 = dx*rs*gg.x + bb.x;
    float o1 = dy*rs*gg.y + bb.y;
    float o2 = dz*rs*gg.z + bb.z;
    float o3 = dw*rs*gg.w + bb.w;
    __nv_bfloat16 h0,h1,h2,h3,l0,l1,l2,l3;
    split_bf16(o0,h0,l0); split_bf16(o1,h1,l1); split_bf16(o2,h2,l2); split_bf16(o3,h3,l3);
    uint2 uh, ul;
    uh.x = ((uint32_t)__bfloat16_as_ushort(h1) << 16) | __bfloat16_as_ushort(h0);
    uh.y = ((uint32_t)__bfloat16_as_ushort(h3) << 16) | __bfloat16_as_ushort(h2);
    ul.x = ((uint32_t)__bfloat16_as_ushort(l1) << 16) | __bfloat16_as_ushort(l0);
    ul.y = ((uint32_t)__bfloat16_as_ushort(l3) << 16) | __bfloat16_as_ushort(l2);
    *reinterpret_cast<uint2*>(yhi + (size_t)row*HIDDEN + lane*4) = uh;
    *reinterpret_cast<uint2*>(ylo + (size_t)row*HIDDEN + lane*4) = ul;
}

// ---------------- fused flash attention (scalar fp32, double-buffered K/V) ------------
#define KTILE 16
#define ATT_THREADS 160
#define QSPLIT0 129
#define ATT_NT   ((SEQ + KTILE - 1) / KTILE)
__global__ void __launch_bounds__(ATT_THREADS)
attention_kernel(const float* __restrict__ qkv, float* __restrict__ out)
{
    __shared__ __align__(16) float Ks[2][KTILE*DHEAD];
    __shared__ __align__(16) float Vs[2][KTILE*DHEAD];
    int bhq = blockIdx.x;
    int half = bhq & 1;
    int bh   = bhq >> 1;
    int b  = bh >> 1, h = bh & 1;
    int tid = threadIdx.x;
    int r    = (half ? QSPLIT0 : 0) + tid;
    int rend = (half ? SEQ : QSPLIT0);
    bool act = (r < rend);
    const float scale = 0.125f;

    int i0 = tid, i1 = tid + ATT_THREADS;
    int j0e = i0 >> 4, e0 = i0 & 15;
    int j1e = i1 >> 4, e1 = i1 & 15;
    const float4* qkv4 = reinterpret_cast<const float4*>(qkv);
    size_t bbase = (size_t)b*SEQ;

    float q[DHEAD], acc[DHEAD];
    float m = -1e30f, l = 0.f;
    if (act) {
        const float4* qrow = qkv4 + (bbase + r)*(3*HIDDEN/4) + h*(DHEAD/4);
        #pragma unroll
        for (int e4=0;e4<DHEAD/4;e4++){
            float4 t = qrow[e4];
            q[e4*4+0]=t.x*scale; q[e4*4+1]=t.y*scale; q[e4*4+2]=t.z*scale; q[e4*4+3]=t.w*scale;
        }
        #pragma unroll
        for (int e=0;e<DHEAD;e++) acc[e]=0.f;
    }
    {
        size_t rb0 = (bbase + j0e)*(3*HIDDEN/4) + h*(DHEAD/4);
        reinterpret_cast<float4*>(Ks[0])[i0] = qkv4[rb0 + (HIDDEN/4)   + e0];
        reinterpret_cast<float4*>(Vs[0])[i0] = qkv4[rb0 + (2*HIDDEN/4) + e0];
        if (i1 < KTILE*16) {
            size_t rb1 = (bbase + j1e)*(3*HIDDEN/4) + h*(DHEAD/4);
            reinterpret_cast<float4*>(Ks[0])[i1] = qkv4[rb1 + (HIDDEN/4)   + e1];
            reinterpret_cast<float4*>(Vs[0])[i1] = qkv4[rb1 + (2*HIDDEN/4) + e1];
        }
    }
    __syncthreads();

    int buf = 0;
    for (int t = 0; t < ATT_NT; t++) {
        int j0 = t*KTILE;
        int jn = SEQ - j0; if (jn > KTILE) jn = KTILE;
        bool more = (t+1 < ATT_NT);
        float4 pk0, pv0, pk1, pv1;
        bool v0f = false, v1f = false;
        if (more) {
            int nj0 = j0 + KTILE;
            int jnn = SEQ - nj0; if (jnn > KTILE) jnn = KTILE;
            int lim = jnn*16;
            v0f = (i0 < lim);
            v1f = (i1 < lim);
            if (v0f) {
                size_t rb = (bbase + nj0 + j0e)*(3*HIDDEN/4) + h*(DHEAD/4);
                pk0 = qkv4[rb + (HIDDEN/4)   + e0];
                pv0 = qkv4[rb + (2*HIDDEN/4) + e0];
            }
            if (v1f) {
                size_t rb = (bbase + nj0 + j1e)*(3*HIDDEN/4) + h*(DHEAD/4);
                pk1 = qkv4[rb + (HIDDEN/4)   + e1];
                pv1 = qkv4[rb + (2*HIDDEN/4) + e1];
            }
        }
        if (act) {
            float s[KTILE];
            float tmax = -1e30f;
            for (int j = 0; j < jn; j++) {
                const float4* kj = reinterpret_cast<const float4*>(Ks[buf] + j*DHEAD);
                float s0=0.f, s1=0.f, s2=0.f, s3=0.f;
                #pragma unroll
                for (int e4=0;e4<DHEAD/4;e4++){
                    float4 kv = kj[e4];
                    s0 += q[e4*4+0]*kv.x;
                    s1 += q[e4*4+1]*kv.y;
                    s2 += q[e4*4+2]*kv.z;
                    s3 += q[e4*4+3]*kv.w;
                }
                s[j] = (s0+s1)+(s2+s3);
                tmax = fmaxf(tmax, s[j]);
            }
            float mnew = fmaxf(m, tmax);
            float corr = expf(m - mnew);
            l *= corr;
            #pragma unroll
            for (int e=0;e<DHEAD;e++) acc[e] *= corr;
            m = mnew;
            for (int j = 0; j < jn; j++) {
                float p = expf(s[j] - mnew);
                l += p;
                const float4* vj = reinterpret_cast<const float4*>(Vs[buf] + j*DHEAD);
                #pragma unroll
                for (int e4=0;e4<DHEAD/4;e4++){
                    float4 vv = vj[e4];
                    acc[e4*4+0] += p*vv.x;
                    acc[e4*4+1] += p*vv.y;
                    acc[e4*4+2] += p*vv.z;
                    acc[e4*4+3] += p*vv.w;
                }
            }
        }
        if (more) {
            int nb = buf ^ 1;
            if (v0f) {
                reinterpret_cast<float4*>(Ks[nb])[i0] = pk0;
                reinterpret_cast<float4*>(Vs[nb])[i0] = pv0;
            }
            if (v1f) {
                reinterpret_cast<float4*>(Ks[nb])[i1] = pk1;
                reinterpret_cast<float4*>(Vs[nb])[i1] = pv1;
            }
            __syncthreads();
            buf = nb;
        }
    }
    if (act) {
        float inv = 1.0f / l;
        float* orow = out + (bbase + r)*HIDDEN + h*DHEAD;
        #pragma unroll
        for (int e=0;e<DHEAD;e++) orow[e] += acc[e]*inv;
    }
}

// ---------------- classifier head + softmax ----------------
__global__ void __launch_bounds__(256)
head_kernel(const float* __restrict__ headb, float* __restrict__ dst)
{
    __shared__ float xs[HIDDEN];
    __shared__ float logits[OUTD];
    __shared__ float red[8];
    __shared__ float sval;
    int b = blockIdx.x, tid = threadIdx.x;
    if (tid < HIDDEN) xs[tid] = g_out[(size_t)b*SEQ*HIDDEN + tid];
    __syncthreads();
    for (int n = tid; n < OUTD; n += 256) {
        float s = headb[n];
        #pragma unroll 8
        for (int k = 0; k < HIDDEN; k++) s += xs[k]*g_headWT[(size_t)k*OUTD + n];
        logits[n] = s;
    }
    __syncthreads();
    float mv = -1e30f;
    for (int n = tid; n < OUTD; n += 256) mv = fmaxf(mv, logits[n]);
    #pragma unroll
    for (int o=16;o;o>>=1) mv = fmaxf(mv, __shfl_xor_sync(0xffffffffu, mv, o));
    if ((tid & 31) == 0) red[tid>>5] = mv;
    __syncthreads();
    if (tid == 0) {
        float t = red[0];
        #pragma unroll
        for (int i=1;i<8;i++) t = fmaxf(t, red[i]);
        sval = t;
    }
    __syncthreads();
    float mx = sval;
    float sum = 0.f;
    for (int n = tid; n < OUTD; n += 256) {
        float e = expf(logits[n] - mx);
        logits[n] = e;
        sum += e;
    }
    #pragma unroll
    for (int o=16;o;o>>=1) sum += __shfl_xor_sync(0xffffffffu, sum, o);
    if ((tid & 31) == 0) red[tid>>5] = sum;
    __syncthreads();
    if (tid == 0) {
        float t = 0.f;
        #pragma unroll
        for (int i=0;i<8;i++) t += red[i];
        sval = t;
    }
    __syncthreads();
    float inv = 1.0f / sval;
    for (int n = tid; n < OUTD; n += 256)
        dst[(size_t)b*OUTD + n] = logits[n]*inv;
}

// ---------------- launch ----------------
extern "C" void kernel_launch(void* const* d_in, const int* in_sizes, int n_in,
                              void* d_out, int out_size)
{
    const float* images = (const float*)d_in[0];
    const float* mapW   = (const float*)d_in[1];
    const float* mapb   = (const float*)d_in[2];
    const float* cls    = (const float*)d_in[3];
    const float* qW     = (const float*)d_in[4];
    const float* qb     = (const float*)d_in[5];
    const float* kW     = (const float*)d_in[6];
    const float* kb     = (const float*)d_in[7];
    const float* vW     = (const float*)d_in[8];
    const float* vb     = (const float*)d_in[9];
    const float* ln1g   = (const float*)d_in[10];
    const float* ln1b   = (const float*)d_in[11];
    const float* ln2g   = (const float*)d_in[12];
    const float* ln2b   = (const float*)d_in[13];
    const float* w1     = (const float*)d_in[14];
    const float* b1     = (const float*)d_in[15];
    const float* w2     = (const float*)d_in[16];
    const float* b2     = (const float*)d_in[17];
    const float* headW  = (const float*)d_in[18];
    const float* headb  = (const float*)d_in[19];
    float* dst = (float*)d_out;

    float *p_out, *p_qkv, *p_qkvB;
    __nv_bfloat16 *p_xhi, *p_xlo, *p_h1hi, *p_h1lo;
    __nv_bfloat16 *p_qWhi, *p_qWlo, *p_w1hi, *p_w1lo, *p_w2hi, *p_w2lo;
    cudaGetSymbolAddress((void**)&p_out,   g_out);
    cudaGetSymbolAddress((void**)&p_qkv,   g_qkv);
    cudaGetSymbolAddress((void**)&p_qkvB,  g_qkvB);
    cudaGetSymbolAddress((void**)&p_xhi,   g_xhi);
    cudaGetSymbolAddress((void**)&p_xlo,   g_xlo);
    cudaGetSymbolAddress((void**)&p_h1hi,  g_h1hi);
    cudaGetSymbolAddress((void**)&p_h1lo,  g_h1lo);
    cudaGetSymbolAddress((void**)&p_qWhi,  g_qkvWhi);
    cudaGetSymbolAddress((void**)&p_qWlo,  g_qkvWlo);
    cudaGetSymbolAddress((void**)&p_w1hi,  g_w1hi);
    cudaGetSymbolAddress((void**)&p_w1lo,  g_w1lo);
    cudaGetSymbolAddress((void**)&p_w2hi,  g_w2hi);
    cudaGetSymbolAddress((void**)&p_w2lo,  g_w2lo);

    prep_kernel<<<(PREP_TOTAL+255)/256, 256>>>(mapW, qW, qb, kW, kb, vW, vb, w1, w2, headW);

    cls_pos_kernel<<<(BATCH*HIDDEN+255)/256, 256>>>(cls);
    patch_embed_kernel<<<dim3(HIDDEN/64, MPATCH/64), 256>>>(images, mapb);

    for (int blk = 0; blk < NBLOCKS; blk++) {
        // LN1 -> x split
        ln_kernel<<<MTOK/8, 256>>>(p_out, ln1g + blk*HIDDEN, ln1b + blk*HIDDEN, p_xhi, p_xlo);
        // qkv projection: (MTOK,128) x (384,128)^T  -> fp32 qkv
        sgemm_mma_kernel<<<dim3(3*HIDDEN/128, MTOK/128), 256>>>(
            p_xhi, p_xlo,
            p_qWhi + (size_t)blk*3*HIDDEN*HIDDEN, p_qWlo + (size_t)blk*3*HIDDEN*HIDDEN,
            p_qkvB + blk*3*HIDDEN, p_qkv, nullptr, nullptr,
            3*HIDDEN, HIDDEN, 0);
        // flash attention (+residual into out)
        attention_kernel<<<BATCH*NHEADS*2, ATT_THREADS>>>(p_qkv, p_out);
        // LN2 -> x split
        ln_kernel<<<MTOK/8, 256>>>(p_out, ln2g + blk*HIDDEN, ln2b + blk*HIDDEN, p_xhi, p_xlo);
        // MLP up + gelu -> h1 split (bf16 hi/lo)
        sgemm_mma_kernel<<<dim3(MLP/128, MTOK/128), 256>>>(
            p_xhi, p_xlo,
            p_w1hi + (size_t)blk*MLP*HIDDEN, p_w1lo + (size_t)blk*MLP*HIDDEN,
            b1 + blk*MLP, nullptr, p_h1hi, p_h1lo,
            MLP, HIDDEN, GF_GELU | GF_BF16);
        // MLP down, accumulate into residual
        sgemm_mma_kernel<<<dim3(HIDDEN/128, MTOK/128), 256>>>(
            p_h1hi, p_h1lo,
            p_w2hi + (size_t)blk*HIDDEN*MLP, p_w2lo + (size_t)blk*HIDDEN*MLP,
            b2 + blk*HIDDEN, p_out, nullptr, nullptr,
            HIDDEN, MLP, GF_ACC);
    }

    head_kernel<<<BATCH, 256>>>(headb, dst);
    (void)in_sizes; (void)n_in; (void)out_size;
}